// round 16
// baseline (speedup 1.0000x reference)
#include <cuda_runtime.h>
#include <cuda_bf16.h>
#include <cuda_fp16.h>

#define NN 20000
#define DD 256
#define D4 64
#define EE 640000
#define MTILES 157   // ceil(20000/128)

#define GSTAGES 4
#define STAGE_BYTES 16384          // A 8KB + B 8KB per stage
#define GEMM_SMEM (GSTAGES * STAGE_BYTES)

#define FILLB ((EE + 255) / 256)   // 2500 fill blocks per relation
#define RSB ((NN + 255) / 256)     // 79 rs blocks per relation

#define HISTB 2500                 // hist blocks per relation (256 thr)
#define WPREPB 1024                // 4 * 256 * 256 / 256
#define XCVTB 5000                 // NN * D4 / 256

// ---------------- static device scratch ----------------
// g_cnt layout: [0,2N) cnt_out[rel], [2N,4N) cnt_in[rel], [4N,6N) cursor[rel]
__device__ int   g_cnt[6 * NN];
__device__ int   g_off[2 * (NN + 1)];
__device__ int   g_csr[2 * EE];
__device__ float g_rs[4 * NN];                        // [0,2N) rs_out, [2N,4N) rs_in
__device__ __align__(16) __half g_xh[NN * DD];        // fp16 gather operand (x, then h)
__device__ __align__(16) __half g_A[2][NN * DD];      // fp16 agg outputs per relation
__device__ __align__(16) __half g_WT[4][DD * DD];     // [layer*2+rel], W^T: [n][k], fp16

static __device__ __forceinline__ unsigned sw64(unsigned o) { return o ^ ((o >> 3) & 0x30); }
static __device__ __forceinline__ unsigned smem_u32(const void* p) {
    unsigned a;
    asm("{ .reg .u64 t; cvta.to.shared.u64 t, %1; cvt.u32.u64 %0, t; }" : "=r"(a) : "l"(p));
    return a;
}
static __device__ __forceinline__ void ldmx4(unsigned addr, unsigned& r0, unsigned& r1,
                                             unsigned& r2, unsigned& r3) {
    asm volatile("ldmatrix.sync.aligned.m8n8.x4.shared.b16 {%0,%1,%2,%3}, [%4];"
                 : "=r"(r0), "=r"(r1), "=r"(r2), "=r"(r3) : "r"(addr));
}
static __device__ __forceinline__ void mma16816(float* c, const unsigned* a,
                                                unsigned b0, unsigned b1) {
    asm volatile(
        "mma.sync.aligned.m16n8k16.row.col.f32.f16.f16.f32 "
        "{%0,%1,%2,%3}, {%4,%5,%6,%7}, {%8,%9}, {%0,%1,%2,%3};"
        : "+f"(c[0]), "+f"(c[1]), "+f"(c[2]), "+f"(c[3])
        : "r"(a[0]), "r"(a[1]), "r"(a[2]), "r"(a[3]), "r"(b0), "r"(b1));
}
static __device__ __forceinline__ void cpasync16(unsigned dst, const void* src, int srcbytes) {
    asm volatile("cp.async.cg.shared.global [%0], [%1], 16, %2;"
                 :: "r"(dst), "l"(src), "r"(srcbytes) : "memory");
}
#define CP_COMMIT() asm volatile("cp.async.commit_group;" ::: "memory")
#define CP_WAIT2()  asm volatile("cp.async.wait_group 2;" ::: "memory")

// ---------------- setup kernels ----------------
__global__ void k_zero_cnt() {
    int i = blockIdx.x * blockDim.x + threadIdx.x;
    if (i < 4 * NN) g_cnt[i] = 0;   // cursors [4N,6N) initialized by k_scan2
}

// heterogeneous launch:
//   blocks [0, 2*HISTB): degree histogram (rel = b / HISTB)
//   blocks [2*HISTB, +WPREPB): weight transpose + fp16 convert (input-only dep)
//   blocks [.., +XCVTB): x fp32 -> fp16 (input-only dep)
__global__ void k_hist_cvt(const int* __restrict__ s0, const int* __restrict__ d0,
                           const int* __restrict__ s1, const int* __restrict__ d1,
                           const float* __restrict__ x,
                           const float* __restrict__ W0, const float* __restrict__ W1,
                           const float* __restrict__ W2, const float* __restrict__ W3) {
    int b = blockIdx.x;
    int t = threadIdx.x;

    if (b < 2 * HISTB) {
        int rel = (b >= HISTB);
        const int* src = rel ? s1 : s0;
        const int* dst = rel ? d1 : d0;
        int i = (b - rel * HISTB) * 256 + t;
        if (i >= EE) return;
        atomicAdd(&g_cnt[rel * NN + src[i]], 1);
        atomicAdd(&g_cnt[2 * NN + rel * NN + dst[i]], 1);
    } else if (b < 2 * HISTB + WPREPB) {
        int e = (b - 2 * HISTB) * 256 + t;   // 0 .. 4*DD*DD-1
        int m = e >> 16;
        int idx = e & 65535;
        int n = idx >> 8, k = idx & 255;
        const float* W = (m == 0) ? W0 : (m == 1) ? W1 : (m == 2) ? W2 : W3;
        g_WT[m][idx] = __float2half_rn(W[k * DD + n]);
    } else {
        int i = (b - 2 * HISTB - WPREPB) * 256 + t;   // one float4 each
        if (i < NN * D4) {
            float4 v = ((const float4*)x)[i];
            uint2 o;
            *(half2*)&o.x = __floats2half2_rn(v.x, v.y);
            *(half2*)&o.y = __floats2half2_rn(v.z, v.w);
            ((uint2*)g_xh)[i] = o;
        }
    }
}

// exclusive scan of in-degree -> CSR offsets; also init fill cursors to off[i]
// (absolute-index cursors: fill's atomicAdd then returns the final CSR slot).
__global__ void k_scan2() {
    int rel = blockIdx.x;
    const int* cnt = g_cnt + 2 * NN + rel * NN;
    int* off = g_off + rel * (NN + 1);
    int* cur = g_cnt + 4 * NN + rel * NN;
    int t = threadIdx.x, lane = t & 31, w = t >> 5;
    int base = t * 20;
    int v[20], cc[20];
    int run = 0;
#pragma unroll
    for (int j = 0; j < 20; j++) {
        int i = base + j;
        int c = (i < NN) ? cnt[i] : 0;
        run += c;
        v[j] = run;
        cc[j] = c;
    }
    int x = run;
#pragma unroll
    for (int d = 1; d < 32; d <<= 1) {
        int y = __shfl_up_sync(0xffffffffu, x, d);
        if (lane >= d) x += y;
    }
    __shared__ int wsum[32];
    if (lane == 31) wsum[w] = x;
    __syncthreads();
    if (w == 0) {
        int s = wsum[lane];
#pragma unroll
        for (int d = 1; d < 32; d <<= 1) {
            int y = __shfl_up_sync(0xffffffffu, s, d);
            if (lane >= d) s += y;
        }
        wsum[lane] = s;
    }
    __syncthreads();
    int excl = x - run + (w > 0 ? wsum[w - 1] : 0);
#pragma unroll
    for (int j = 0; j < 20; j++) {
        int i = base + j;
        if (i < NN) {
            int o = excl + v[j];
            off[i + 1] = o;
            cur[i] = o - cc[j];   // = off[i]
        }
    }
    if (t == 0) off[0] = 0;
}

// heterogeneous launch: blocks [0,FILLB) fill CSR (absolute cursors);
// blocks [FILLB,FILLB+RSB) compute rs. Both depend only on the scan.
__global__ void k_fill_rs(const int* __restrict__ s0, const int* __restrict__ d0,
                          const int* __restrict__ s1, const int* __restrict__ d1) {
    int rel = blockIdx.y;
    int bx = blockIdx.x;
    if (bx < FILLB) {
        const int* src = rel ? s1 : s0;
        const int* dst = rel ? d1 : d0;
        int i = bx * blockDim.x + threadIdx.x;
        if (i >= EE) return;
        int d = dst[i];
        int pos = atomicAdd(&g_cnt[4 * NN + rel * NN + d], 1);   // absolute CSR slot
        g_csr[rel * EE + pos] = src[i];
    } else {
        int i = (bx - FILLB) * blockDim.x + threadIdx.x;
        if (i >= NN) return;
        float co = (float)g_cnt[rel * NN + i];
        float ci = (float)g_cnt[2 * NN + rel * NN + i];
        g_rs[rel * NN + i]          = rsqrtf(fmaxf(co, 1.0f));
        g_rs[2 * NN + rel * NN + i] = rsqrtf(fmaxf(ci, 1.0f));
    }
}

// ---------------- aggregation: fp16 gather rows, fp32 accumulate, fp16 out -------
// 32 threads per node (one uint4 = 8 halves per thread), 8 nodes per 256-block.
__global__ void k_agg() {
    int rel = blockIdx.y;
    int node = blockIdx.x * 8 + (threadIdx.x >> 5);
    int t = threadIdx.x & 31;
    if (node >= NN) return;

    const uint4* x4 = (const uint4*)g_xh;   // 32 uint4 per 512B row
    const int* off = g_off + rel * (NN + 1);
    const int* csr = g_csr + rel * EE;
    const float* rs_out = g_rs + rel * NN;

    int beg = off[node], end = off[node + 1];
    float acc[8] = {0.f, 0.f, 0.f, 0.f, 0.f, 0.f, 0.f, 0.f};
#pragma unroll 4
    for (int e = beg; e < end; e++) {
        int s = __ldg(&csr[e]);
        float sc = __ldg(&rs_out[s]);
        uint4 v = __ldg(&x4[s * 32 + t]);
        float2 f0 = __half22float2(*(half2*)&v.x);
        float2 f1 = __half22float2(*(half2*)&v.y);
        float2 f2 = __half22float2(*(half2*)&v.z);
        float2 f3 = __half22float2(*(half2*)&v.w);
        acc[0] += f0.x * sc; acc[1] += f0.y * sc;
        acc[2] += f1.x * sc; acc[3] += f1.y * sc;
        acc[4] += f2.x * sc; acc[5] += f2.y * sc;
        acc[6] += f3.x * sc; acc[7] += f3.y * sc;
    }
    float ri = g_rs[2 * NN + rel * NN + node];

    uint4 o;
    half2* oh = (half2*)&o;
#pragma unroll
    for (int j = 0; j < 4; j++)
        oh[j] = __floats2half2_rn(acc[2 * j] * ri, acc[2 * j + 1] * ri);
    *(uint4*)&g_A[rel][(size_t)node * DD + t * 8] = o;
}

// ---------------- HMMA GEMM (cp.async 4-stage): C = aggS@Ws + aggU@Wu + b (+relu)
// fp16 operands, fp32 accum. 2 terms x K=256 = effective K 512, chunks of 32 (16).
// CTA 128(M) x 128(N), 8 warps, warp tile 32x64. Stage = A 8KB + B 8KB.
template <bool RELU, bool TO_H>
__global__ void __launch_bounds__(256)
k_hgemm(int layer, const float* __restrict__ b0v, const float* __restrict__ b1v,
        float* __restrict__ Cext) {
    extern __shared__ __align__(1024) char smem[];

    const int tid = threadIdx.x;
    const int lane = tid & 31;
    const int wid = tid >> 5;
    const int wm = wid >> 1;
    const int wn = wid & 1;
    const int bm = blockIdx.y * 128;
    const int bn = blockIdx.x * 128;

    const __half* AS = g_A[0];
    const __half* AU = g_A[1];
    const __half* BS = g_WT[layer * 2 + 0];
    const __half* BU = g_WT[layer * 2 + 1];

    unsigned sbase = smem_u32(smem);
    unsigned aoff = (unsigned)((wm * 32 + ((lane >> 3) & 1) * 8 + (lane & 7)) * 64
                               + ((lane >> 4) & 1) * 16);
    unsigned boff = (unsigned)((wn * 64 + ((lane >> 4) & 1) * 8 + (lane & 7)) * 64
                               + ((lane >> 3) & 1) * 16);
    unsigned aAdr[GSTAGES][2], bAdr[GSTAGES][2];
#pragma unroll
    for (int buf = 0; buf < GSTAGES; buf++)
#pragma unroll
        for (int ks = 0; ks < 2; ks++) {
            aAdr[buf][ks] = sbase + buf * STAGE_BYTES + sw64(aoff + ks * 32);
            bAdr[buf][ks] = sbase + buf * STAGE_BYTES + 8192 + sw64(boff + ks * 32);
        }

    const int r0 = tid >> 2, ch = tid & 3;
    const unsigned st0 = sw64((unsigned)(r0 * 64 + ch * 16));
    const unsigned st1 = sw64((unsigned)((r0 + 64) * 64 + ch * 16));
    const int gr0 = bm + r0, gr1 = bm + 64 + r0;
    const int a0ok = (gr0 < NN) ? 16 : 0;
    const int a1ok = (gr1 < NN) ? 16 : 0;

    auto issue = [&](int cn, int buf) {
        int term = cn >> 3;
        int kk = (cn & 7) * 32;
        const __half* Ag = term ? AU : AS;
        const __half* Bg = term ? BU : BS;
        unsigned ab = sbase + buf * STAGE_BYTES;
        unsigned bb = ab + 8192;
        cpasync16(ab + st0, Ag + (size_t)gr0 * DD + kk + ch * 8, a0ok);
        cpasync16(ab + st1, Ag + (size_t)gr1 * DD + kk + ch * 8, a1ok);
        cpasync16(bb + st0, Bg + (size_t)(bn + r0) * DD + kk + ch * 8, 16);
        cpasync16(bb + st1, Bg + (size_t)(bn + 64 + r0) * DD + kk + ch * 8, 16);
    };

    float acc[2][8][4];
#pragma unroll
    for (int i = 0; i < 2; i++)
#pragma unroll
        for (int j = 0; j < 8; j++)
#pragma unroll
            for (int q = 0; q < 4; q++) acc[i][j][q] = 0.f;

#pragma unroll
    for (int s = 0; s < GSTAGES - 1; s++) {
        issue(s, s);
        CP_COMMIT();
    }

    for (int c = 0; c < 16; c++) {
        int buf = c & (GSTAGES - 1);
        CP_WAIT2();
        __syncthreads();

#pragma unroll
        for (int ks = 0; ks < 2; ks++) {
            unsigned a[2][4];
            ldmx4(aAdr[buf][ks],        a[0][0], a[0][1], a[0][2], a[0][3]);
            ldmx4(aAdr[buf][ks] + 1024, a[1][0], a[1][1], a[1][2], a[1][3]);
#pragma unroll
            for (int p = 0; p < 4; p++) {
                unsigned bb0, bb1, bb2, bb3;
                ldmx4(bAdr[buf][ks] + p * 1024, bb0, bb1, bb2, bb3);
#pragma unroll
                for (int mt = 0; mt < 2; mt++) {
                    mma16816(acc[mt][2 * p + 0], a[mt], bb0, bb1);
                    mma16816(acc[mt][2 * p + 1], a[mt], bb2, bb3);
                }
            }
        }

        if (c + GSTAGES - 1 < 16) issue(c + GSTAGES - 1, (c + GSTAGES - 1) & (GSTAGES - 1));
        CP_COMMIT();
    }

    // epilogue: bias + (relu) + store
#pragma unroll
    for (int nt = 0; nt < 8; nt++) {
        int col = bn + wn * 64 + nt * 8 + (lane & 3) * 2;
        float bs0 = b0v[col] + b1v[col];
        float bs1 = b0v[col + 1] + b1v[col + 1];
#pragma unroll
        for (int mt = 0; mt < 2; mt++) {
            int row = bm + wm * 32 + mt * 16 + (lane >> 2);
#pragma unroll
            for (int half_sel = 0; half_sel < 2; half_sel++) {
                int r = row + half_sel * 8;
                if (r < NN) {
                    float vx = acc[mt][nt][2 * half_sel + 0] + bs0;
                    float vy = acc[mt][nt][2 * half_sel + 1] + bs1;
                    if (RELU) { vx = fmaxf(vx, 0.f); vy = fmaxf(vy, 0.f); }
                    if (TO_H) {
                        *(half2*)(g_xh + (size_t)r * DD + col) = __floats2half2_rn(vx, vy);
                    } else {
                        float2 v2 = make_float2(vx, vy);
                        *(float2*)(Cext + (size_t)r * DD + col) = v2;
                    }
                }
            }
        }
    }
}

// ---------------- launch ----------------
extern "C" void kernel_launch(void* const* d_in, const int* in_sizes, int n_in,
                              void* d_out, int out_size) {
    const float* x    = (const float*)d_in[0];
    const int* s_src  = (const int*)d_in[1];
    const int* s_dst  = (const int*)d_in[2];
    const int* u_src  = (const int*)d_in[3];
    const int* u_dst  = (const int*)d_in[4];
    const float* W1s  = (const float*)d_in[5];
    const float* b1s  = (const float*)d_in[6];
    const float* W1u  = (const float*)d_in[7];
    const float* b1u  = (const float*)d_in[8];
    const float* W2s  = (const float*)d_in[9];
    const float* b2s  = (const float*)d_in[10];
    const float* W2u  = (const float*)d_in[11];
    const float* b2u  = (const float*)d_in[12];
    float* out = (float*)d_out;

    static int attr_done = 0;
    if (!attr_done) {
        cudaFuncSetAttribute(k_hgemm<true, true>,
                             cudaFuncAttributeMaxDynamicSharedMemorySize, GEMM_SMEM);
        cudaFuncSetAttribute(k_hgemm<false, false>,
                             cudaFuncAttributeMaxDynamicSharedMemorySize, GEMM_SMEM);
        attr_done = 1;
    }

    k_zero_cnt<<<(4 * NN + 255) / 256, 256>>>();
    k_hist_cvt<<<2 * HISTB + WPREPB + XCVTB, 256>>>(s_src, s_dst, u_src, u_dst,
                                                    x, W1s, W1u, W2s, W2u);
    k_scan2<<<2, 1024>>>();
    k_fill_rs<<<dim3(FILLB + RSB, 2), 256>>>(s_src, s_dst, u_src, u_dst);

    dim3 ggrid(2, MTILES);

    // layer 1: agg from g_xh(=x), GEMM -> relu -> g_xh(=h, fp16)
    k_agg<<<dim3((NN + 7) / 8, 2), 256>>>();
    k_hgemm<true, true><<<ggrid, 256, GEMM_SMEM>>>(0, b1s, b1u, nullptr);
    // layer 2: agg from g_xh(=h), GEMM -> out
    k_agg<<<dim3((NN + 7) / 8, 2), 256>>>();
    k_hgemm<false, false><<<ggrid, 256, GEMM_SMEM>>>(1, b2s, b2u, out);
}

// round 17
// speedup vs baseline: 1.0437x; 1.0437x over previous
#include <cuda_runtime.h>
#include <cuda_bf16.h>
#include <cuda_fp16.h>

#define NN 20000
#define DD 256
#define D4 64
#define EE 640000
#define MTILES 157   // ceil(20000/128)

#define GSTAGES 4
#define STAGE_BYTES 16384          // A 8KB + B 8KB per stage
#define GEMM_SMEM (GSTAGES * STAGE_BYTES)

#define FILLB ((EE + 255) / 256)   // 2500 fill blocks per relation
#define RSB ((NN + 255) / 256)     // 79 rs blocks per relation

#define HISTB 2500                 // hist blocks per relation (256 thr)
#define WPREPB 1024                // 4 * 256 * 256 / 256
#define XCVTB 5000                 // NN * D4 / 256

// ---------------- static device scratch ----------------
// g_cnt layout: [0,2N) cnt_out[rel], [2N,4N) cnt_in[rel], [4N,6N) cursor[rel]
__device__ int   g_cnt[6 * NN];
__device__ int   g_off[2 * (NN + 1)];
__device__ int   g_csr[2 * EE];
__device__ float g_rs[4 * NN];                        // [0,2N) rs_out, [2N,4N) rs_in
__device__ __align__(16) __half g_xh[NN * DD];        // fp16 gather operand (x, then h)
__device__ __align__(16) __half g_A[2][NN * DD];      // fp16 agg outputs per relation
__device__ __align__(16) __half g_WT[4][DD * DD];     // [layer*2+rel], W^T: [n][k], fp16

static __device__ __forceinline__ unsigned sw64(unsigned o) { return o ^ ((o >> 3) & 0x30); }
static __device__ __forceinline__ unsigned smem_u32(const void* p) {
    unsigned a;
    asm("{ .reg .u64 t; cvta.to.shared.u64 t, %1; cvt.u32.u64 %0, t; }" : "=r"(a) : "l"(p));
    return a;
}
static __device__ __forceinline__ void ldmx4(unsigned addr, unsigned& r0, unsigned& r1,
                                             unsigned& r2, unsigned& r3) {
    asm volatile("ldmatrix.sync.aligned.m8n8.x4.shared.b16 {%0,%1,%2,%3}, [%4];"
                 : "=r"(r0), "=r"(r1), "=r"(r2), "=r"(r3) : "r"(addr));
}
static __device__ __forceinline__ void mma16816(float* c, const unsigned* a,
                                                unsigned b0, unsigned b1) {
    asm volatile(
        "mma.sync.aligned.m16n8k16.row.col.f32.f16.f16.f32 "
        "{%0,%1,%2,%3}, {%4,%5,%6,%7}, {%8,%9}, {%0,%1,%2,%3};"
        : "+f"(c[0]), "+f"(c[1]), "+f"(c[2]), "+f"(c[3])
        : "r"(a[0]), "r"(a[1]), "r"(a[2]), "r"(a[3]), "r"(b0), "r"(b1));
}
static __device__ __forceinline__ void cpasync16(unsigned dst, const void* src, int srcbytes) {
    asm volatile("cp.async.cg.shared.global [%0], [%1], 16, %2;"
                 :: "r"(dst), "l"(src), "r"(srcbytes) : "memory");
}
#define CP_COMMIT() asm volatile("cp.async.commit_group;" ::: "memory")
#define CP_WAIT2()  asm volatile("cp.async.wait_group 2;" ::: "memory")

// ---------------- setup kernels ----------------
__global__ void k_zero_cnt() {
    int i = blockIdx.x * blockDim.x + threadIdx.x;
    if (i < 6 * NN) g_cnt[i] = 0;
}

// heterogeneous launch:
//   blocks [0, 2*HISTB): degree histogram (rel = b / HISTB)
//   blocks [2*HISTB, +WPREPB): weight transpose + fp16 convert (input-only dep)
//   blocks [.., +XCVTB): x fp32 -> fp16 (input-only dep)
__global__ void k_hist_cvt(const int* __restrict__ s0, const int* __restrict__ d0,
                           const int* __restrict__ s1, const int* __restrict__ d1,
                           const float* __restrict__ x,
                           const float* __restrict__ W0, const float* __restrict__ W1,
                           const float* __restrict__ W2, const float* __restrict__ W3) {
    int b = blockIdx.x;
    int t = threadIdx.x;

    if (b < 2 * HISTB) {
        int rel = (b >= HISTB);
        const int* src = rel ? s1 : s0;
        const int* dst = rel ? d1 : d0;
        int i = (b - rel * HISTB) * 256 + t;
        if (i >= EE) return;
        atomicAdd(&g_cnt[rel * NN + src[i]], 1);
        atomicAdd(&g_cnt[2 * NN + rel * NN + dst[i]], 1);
    } else if (b < 2 * HISTB + WPREPB) {
        int e = (b - 2 * HISTB) * 256 + t;   // 0 .. 4*DD*DD-1
        int m = e >> 16;
        int idx = e & 65535;
        int n = idx >> 8, k = idx & 255;
        const float* W = (m == 0) ? W0 : (m == 1) ? W1 : (m == 2) ? W2 : W3;
        g_WT[m][idx] = __float2half_rn(W[k * DD + n]);
    } else {
        int i = (b - 2 * HISTB - WPREPB) * 256 + t;   // one float4 each
        if (i < NN * D4) {
            float4 v = ((const float4*)x)[i];
            uint2 o;
            *(half2*)&o.x = __floats2half2_rn(v.x, v.y);
            *(half2*)&o.y = __floats2half2_rn(v.z, v.w);
            ((uint2*)g_xh)[i] = o;
        }
    }
}

// fast exclusive scan: one block of 1024 per relation, 20 elems/thread
__global__ void k_scan2() {
    int rel = blockIdx.x;
    const int* cnt = g_cnt + 2 * NN + rel * NN;
    int* off = g_off + rel * (NN + 1);
    int t = threadIdx.x, lane = t & 31, w = t >> 5;
    int base = t * 20;
    int v[20];
    int run = 0;
#pragma unroll
    for (int j = 0; j < 20; j++) {
        int i = base + j;
        int c = (i < NN) ? cnt[i] : 0;
        run += c;
        v[j] = run;
    }
    int x = run;
#pragma unroll
    for (int d = 1; d < 32; d <<= 1) {
        int y = __shfl_up_sync(0xffffffffu, x, d);
        if (lane >= d) x += y;
    }
    __shared__ int wsum[32];
    if (lane == 31) wsum[w] = x;
    __syncthreads();
    if (w == 0) {
        int s = wsum[lane];
#pragma unroll
        for (int d = 1; d < 32; d <<= 1) {
            int y = __shfl_up_sync(0xffffffffu, s, d);
            if (lane >= d) s += y;
        }
        wsum[lane] = s;
    }
    __syncthreads();
    int excl = x - run + (w > 0 ? wsum[w - 1] : 0);
#pragma unroll
    for (int j = 0; j < 20; j++) {
        int i = base + j;
        if (i < NN) off[i + 1] = excl + v[j];
    }
    if (t == 0) off[0] = 0;
}

// heterogeneous launch: blocks [0,FILLB) fill CSR; blocks [FILLB,FILLB+RSB) compute rs.
__global__ void k_fill_rs(const int* __restrict__ s0, const int* __restrict__ d0,
                          const int* __restrict__ s1, const int* __restrict__ d1) {
    int rel = blockIdx.y;
    int bx = blockIdx.x;
    if (bx < FILLB) {
        const int* src = rel ? s1 : s0;
        const int* dst = rel ? d1 : d0;
        int i = bx * blockDim.x + threadIdx.x;
        if (i >= EE) return;
        int d = dst[i];
        int pos = atomicAdd(&g_cnt[4 * NN + rel * NN + d], 1);
        g_csr[rel * EE + g_off[rel * (NN + 1) + d] + pos] = src[i];
    } else {
        int i = (bx - FILLB) * blockDim.x + threadIdx.x;
        if (i >= NN) return;
        float co = (float)g_cnt[rel * NN + i];
        float ci = (float)g_cnt[2 * NN + rel * NN + i];
        g_rs[rel * NN + i]          = rsqrtf(fmaxf(co, 1.0f));
        g_rs[2 * NN + rel * NN + i] = rsqrtf(fmaxf(ci, 1.0f));
    }
}

// ---------------- aggregation: fp16 gather rows, fp32 accumulate, fp16 out -------
// 32 threads per node (one uint4 = 8 halves per thread), 8 nodes per 256-block.
__global__ void k_agg() {
    int rel = blockIdx.y;
    int node = blockIdx.x * 8 + (threadIdx.x >> 5);
    int t = threadIdx.x & 31;
    if (node >= NN) return;

    const uint4* x4 = (const uint4*)g_xh;   // 32 uint4 per 512B row
    const int* off = g_off + rel * (NN + 1);
    const int* csr = g_csr + rel * EE;
    const float* rs_out = g_rs + rel * NN;

    int beg = off[node], end = off[node + 1];
    float acc[8] = {0.f, 0.f, 0.f, 0.f, 0.f, 0.f, 0.f, 0.f};
#pragma unroll 4
    for (int e = beg; e < end; e++) {
        int s = __ldg(&csr[e]);
        float sc = __ldg(&rs_out[s]);
        uint4 v = __ldg(&x4[s * 32 + t]);
        float2 f0 = __half22float2(*(half2*)&v.x);
        float2 f1 = __half22float2(*(half2*)&v.y);
        float2 f2 = __half22float2(*(half2*)&v.z);
        float2 f3 = __half22float2(*(half2*)&v.w);
        acc[0] += f0.x * sc; acc[1] += f0.y * sc;
        acc[2] += f1.x * sc; acc[3] += f1.y * sc;
        acc[4] += f2.x * sc; acc[5] += f2.y * sc;
        acc[6] += f3.x * sc; acc[7] += f3.y * sc;
    }
    float ri = g_rs[2 * NN + rel * NN + node];

    uint4 o;
    half2* oh = (half2*)&o;
#pragma unroll
    for (int j = 0; j < 4; j++)
        oh[j] = __floats2half2_rn(acc[2 * j] * ri, acc[2 * j + 1] * ri);
    *(uint4*)&g_A[rel][(size_t)node * DD + t * 8] = o;
}

// ---------------- HMMA GEMM (cp.async 4-stage): C = aggS@Ws + aggU@Wu + b (+relu)
// fp16 operands, fp32 accum. 2 terms x K=256 = effective K 512, chunks of 32 (16).
// CTA 128(M) x 128(N), 8 warps, warp tile 32x64. Stage = A 8KB + B 8KB.
template <bool RELU, bool TO_H>
__global__ void __launch_bounds__(256)
k_hgemm(int layer, const float* __restrict__ b0v, const float* __restrict__ b1v,
        float* __restrict__ Cext) {
    extern __shared__ __align__(1024) char smem[];

    const int tid = threadIdx.x;
    const int lane = tid & 31;
    const int wid = tid >> 5;
    const int wm = wid >> 1;
    const int wn = wid & 1;
    const int bm = blockIdx.y * 128;
    const int bn = blockIdx.x * 128;

    const __half* AS = g_A[0];
    const __half* AU = g_A[1];
    const __half* BS = g_WT[layer * 2 + 0];
    const __half* BU = g_WT[layer * 2 + 1];

    unsigned sbase = smem_u32(smem);
    unsigned aoff = (unsigned)((wm * 32 + ((lane >> 3) & 1) * 8 + (lane & 7)) * 64
                               + ((lane >> 4) & 1) * 16);
    unsigned boff = (unsigned)((wn * 64 + ((lane >> 4) & 1) * 8 + (lane & 7)) * 64
                               + ((lane >> 3) & 1) * 16);
    unsigned aAdr[GSTAGES][2], bAdr[GSTAGES][2];
#pragma unroll
    for (int buf = 0; buf < GSTAGES; buf++)
#pragma unroll
        for (int ks = 0; ks < 2; ks++) {
            aAdr[buf][ks] = sbase + buf * STAGE_BYTES + sw64(aoff + ks * 32);
            bAdr[buf][ks] = sbase + buf * STAGE_BYTES + 8192 + sw64(boff + ks * 32);
        }

    const int r0 = tid >> 2, ch = tid & 3;
    const unsigned st0 = sw64((unsigned)(r0 * 64 + ch * 16));
    const unsigned st1 = sw64((unsigned)((r0 + 64) * 64 + ch * 16));
    const int gr0 = bm + r0, gr1 = bm + 64 + r0;
    const int a0ok = (gr0 < NN) ? 16 : 0;
    const int a1ok = (gr1 < NN) ? 16 : 0;

    auto issue = [&](int cn, int buf) {
        int term = cn >> 3;
        int kk = (cn & 7) * 32;
        const __half* Ag = term ? AU : AS;
        const __half* Bg = term ? BU : BS;
        unsigned ab = sbase + buf * STAGE_BYTES;
        unsigned bb = ab + 8192;
        cpasync16(ab + st0, Ag + (size_t)gr0 * DD + kk + ch * 8, a0ok);
        cpasync16(ab + st1, Ag + (size_t)gr1 * DD + kk + ch * 8, a1ok);
        cpasync16(bb + st0, Bg + (size_t)(bn + r0) * DD + kk + ch * 8, 16);
        cpasync16(bb + st1, Bg + (size_t)(bn + 64 + r0) * DD + kk + ch * 8, 16);
    };

    float acc[2][8][4];
#pragma unroll
    for (int i = 0; i < 2; i++)
#pragma unroll
        for (int j = 0; j < 8; j++)
#pragma unroll
            for (int q = 0; q < 4; q++) acc[i][j][q] = 0.f;

#pragma unroll
    for (int s = 0; s < GSTAGES - 1; s++) {
        issue(s, s);
        CP_COMMIT();
    }

    for (int c = 0; c < 16; c++) {
        int buf = c & (GSTAGES - 1);
        CP_WAIT2();
        __syncthreads();

#pragma unroll
        for (int ks = 0; ks < 2; ks++) {
            unsigned a[2][4];
            ldmx4(aAdr[buf][ks],        a[0][0], a[0][1], a[0][2], a[0][3]);
            ldmx4(aAdr[buf][ks] + 1024, a[1][0], a[1][1], a[1][2], a[1][3]);
#pragma unroll
            for (int p = 0; p < 4; p++) {
                unsigned bb0, bb1, bb2, bb3;
                ldmx4(bAdr[buf][ks] + p * 1024, bb0, bb1, bb2, bb3);
#pragma unroll
                for (int mt = 0; mt < 2; mt++) {
                    mma16816(acc[mt][2 * p + 0], a[mt], bb0, bb1);
                    mma16816(acc[mt][2 * p + 1], a[mt], bb2, bb3);
                }
            }
        }

        if (c + GSTAGES - 1 < 16) issue(c + GSTAGES - 1, (c + GSTAGES - 1) & (GSTAGES - 1));
        CP_COMMIT();
    }

    // epilogue: bias + (relu) + store
#pragma unroll
    for (int nt = 0; nt < 8; nt++) {
        int col = bn + wn * 64 + nt * 8 + (lane & 3) * 2;
        float bs0 = b0v[col] + b1v[col];
        float bs1 = b0v[col + 1] + b1v[col + 1];
#pragma unroll
        for (int mt = 0; mt < 2; mt++) {
            int row = bm + wm * 32 + mt * 16 + (lane >> 2);
#pragma unroll
            for (int half_sel = 0; half_sel < 2; half_sel++) {
                int r = row + half_sel * 8;
                if (r < NN) {
                    float vx = acc[mt][nt][2 * half_sel + 0] + bs0;
                    float vy = acc[mt][nt][2 * half_sel + 1] + bs1;
                    if (RELU) { vx = fmaxf(vx, 0.f); vy = fmaxf(vy, 0.f); }
                    if (TO_H) {
                        *(half2*)(g_xh + (size_t)r * DD + col) = __floats2half2_rn(vx, vy);
                    } else {
                        float2 v2 = make_float2(vx, vy);
                        *(float2*)(Cext + (size_t)r * DD + col) = v2;
                    }
                }
            }
        }
    }
}

// ---------------- launch ----------------
extern "C" void kernel_launch(void* const* d_in, const int* in_sizes, int n_in,
                              void* d_out, int out_size) {
    const float* x    = (const float*)d_in[0];
    const int* s_src  = (const int*)d_in[1];
    const int* s_dst  = (const int*)d_in[2];
    const int* u_src  = (const int*)d_in[3];
    const int* u_dst  = (const int*)d_in[4];
    const float* W1s  = (const float*)d_in[5];
    const float* b1s  = (const float*)d_in[6];
    const float* W1u  = (const float*)d_in[7];
    const float* b1u  = (const float*)d_in[8];
    const float* W2s  = (const float*)d_in[9];
    const float* b2s  = (const float*)d_in[10];
    const float* W2u  = (const float*)d_in[11];
    const float* b2u  = (const float*)d_in[12];
    float* out = (float*)d_out;

    static int attr_done = 0;
    if (!attr_done) {
        cudaFuncSetAttribute(k_hgemm<true, true>,
                             cudaFuncAttributeMaxDynamicSharedMemorySize, GEMM_SMEM);
        cudaFuncSetAttribute(k_hgemm<false, false>,
                             cudaFuncAttributeMaxDynamicSharedMemorySize, GEMM_SMEM);
        attr_done = 1;
    }

    k_zero_cnt<<<(6 * NN + 255) / 256, 256>>>();
    k_hist_cvt<<<2 * HISTB + WPREPB + XCVTB, 256>>>(s_src, s_dst, u_src, u_dst,
                                                    x, W1s, W1u, W2s, W2u);
    k_scan2<<<2, 1024>>>();
    k_fill_rs<<<dim3(FILLB + RSB, 2), 256>>>(s_src, s_dst, u_src, u_dst);

    dim3 ggrid(2, MTILES);

    // layer 1: agg from g_xh(=x), GEMM -> relu -> g_xh(=h, fp16)
    k_agg<<<dim3((NN + 7) / 8, 2), 256>>>();
    k_hgemm<true, true><<<ggrid, 256, GEMM_SMEM>>>(0, b1s, b1u, nullptr);
    // layer 2: agg from g_xh(=h), GEMM -> out
    k_agg<<<dim3((NN + 7) / 8, 2), 256>>>();
    k_hgemm<false, false><<<ggrid, 256, GEMM_SMEM>>>(1, b2s, b2u, out);
}